// round 2
// baseline (speedup 1.0000x reference)
#include <cuda_runtime.h>

// Problem constants (fixed shapes per reference: B=8, N=2048, H=128)
#define EPSF 1e-8f
constexpr int B  = 8;
constexpr int Nn = 2048;
constexpr int H  = 128;
constexpr int TM = 64;          // tile of rows per block
constexpr int LD = 132;         // padded leading dim for H-wide smem tiles (bank spread)
constexpr int SLD = 68;         // padded leading dim for S tile

// Scratch (device globals: allocation-free rule)
__device__ float g_n1[B * Nn * H];
__device__ float g_n2[B * Nn * H];
__device__ float g_agg1[B * Nn * H];
__device__ float g_agg2[B * Nn * H];

// ---------------------------------------------------------------------------
// Kernel 1: row-normalize h1 -> g_n1, h2 -> g_n2. One warp per row (H=128).
// ---------------------------------------------------------------------------
__global__ void normalize_kernel(const float* __restrict__ h1,
                                 const float* __restrict__ h2) {
    int warp = (blockIdx.x * blockDim.x + threadIdx.x) >> 5;
    int lane = threadIdx.x & 31;
    const float* src;
    float* dst;
    int row;
    if (warp < B * Nn) { src = h1; dst = g_n1; row = warp; }
    else               { src = h2; dst = g_n2; row = warp - B * Nn; }

    float4 v = ((const float4*)(src + (size_t)row * H))[lane];
    float ss = v.x * v.x + v.y * v.y + v.z * v.z + v.w * v.w;
#pragma unroll
    for (int o = 16; o; o >>= 1) ss += __shfl_xor_sync(0xffffffffu, ss, o);
    float inv = 1.0f / fmaxf(sqrtf(ss), EPSF);
    float4 r = make_float4(v.x * inv, v.y * inv, v.z * inv, v.w * inv);
    ((float4*)(dst + (size_t)row * H))[lane] = r;
}

// ---------------------------------------------------------------------------
// Kernel 2: fused "attention" aggregation (no softmax).
//   dir 0: agg1[b,i,:] = sum_j (n1_i . n2_j) * h2[b,j,:]
//   dir 1: agg2[b,j,:] = sum_i (n1_i . n2_j) * h1[b,i,:]   (Q<->K swap)
// Block: 256 threads, TM=64 query rows, stream key tiles of 64.
// ---------------------------------------------------------------------------
__global__ void agg_kernel(const float* __restrict__ h1,
                           const float* __restrict__ h2) {
    extern __shared__ float sm[];
    float* Qs = sm;               // TM*LD
    float* Ks = Qs + TM * LD;     // TM*LD
    float* Vs = Ks + TM * LD;     // TM*LD
    float* Ss = Vs + TM * LD;     // TM*SLD

    const int tid = threadIdx.x;
    const int b = blockIdx.y, mt = blockIdx.x, dir = blockIdx.z;
    const float* Q = dir == 0 ? g_n1 : g_n2;
    const float* K = dir == 0 ? g_n2 : g_n1;
    const float* V = dir == 0 ? h2 : h1;
    float* O       = dir == 0 ? g_agg1 : g_agg2;

    const float* Qb = Q + (size_t)(b * Nn + mt * TM) * H;
    for (int i = tid; i < TM * (H / 4); i += 256) {
        int r = i >> 5, c4 = (i & 31) << 2;
        *(float4*)&Qs[r * LD + c4] = *(const float4*)&Qb[r * H + c4];
    }

    float acc[8][4];
#pragma unroll
    for (int i = 0; i < 8; i++)
#pragma unroll
        for (int j = 0; j < 4; j++) acc[i][j] = 0.0f;

    const int ty = tid >> 4, tx = tid & 15;
    const int r0 = ty * 4, c0 = tx * 4;
    const int rg = tid >> 5, ct = tid & 31;

    for (int jt = 0; jt < Nn / TM; ++jt) {
        __syncthreads();  // previous iter done with Ks/Vs/Ss
        const float* Kb = K + (size_t)(b * Nn + jt * TM) * H;
        const float* Vb = V + (size_t)(b * Nn + jt * TM) * H;
        for (int i = tid; i < TM * (H / 4); i += 256) {
            int r = i >> 5, c4 = (i & 31) << 2;
            *(float4*)&Ks[r * LD + c4] = *(const float4*)&Kb[r * H + c4];
            *(float4*)&Vs[r * LD + c4] = *(const float4*)&Vb[r * H + c4];
        }
        __syncthreads();

        // S[64,64] = Qtile @ Ktile^T  (4x4 micro-tile per thread)
        float s[4][4];
#pragma unroll
        for (int i = 0; i < 4; i++)
#pragma unroll
            for (int j = 0; j < 4; j++) s[i][j] = 0.0f;

#pragma unroll 4
        for (int k4 = 0; k4 < H; k4 += 4) {
            float4 a[4], bb[4];
#pragma unroll
            for (int i = 0; i < 4; i++) a[i] = *(float4*)&Qs[(r0 + i) * LD + k4];
#pragma unroll
            for (int j = 0; j < 4; j++) bb[j] = *(float4*)&Ks[(c0 + j) * LD + k4];
#pragma unroll
            for (int i = 0; i < 4; i++)
#pragma unroll
                for (int j = 0; j < 4; j++)
                    s[i][j] += a[i].x * bb[j].x + a[i].y * bb[j].y +
                               a[i].z * bb[j].z + a[i].w * bb[j].w;
        }
#pragma unroll
        for (int i = 0; i < 4; i++)
            *(float4*)&Ss[(r0 + i) * SLD + c0] =
                make_float4(s[i][0], s[i][1], s[i][2], s[i][3]);
        __syncthreads();

        // acc[64,128] += S[64,64] @ Vtile[64,128]
        // thread owns 8 rows (rg) x 4 cols (ct*4)
#pragma unroll 2
        for (int k = 0; k < TM; k += 4) {
            float4 sv[8];
#pragma unroll
            for (int i = 0; i < 8; i++) sv[i] = *(float4*)&Ss[(rg * 8 + i) * SLD + k];
#pragma unroll
            for (int kk = 0; kk < 4; kk++) {
                float4 v = *(float4*)&Vs[(k + kk) * LD + ct * 4];
#pragma unroll
                for (int i = 0; i < 8; i++) {
                    float sc = (&sv[i].x)[kk];
                    acc[i][0] += sc * v.x;
                    acc[i][1] += sc * v.y;
                    acc[i][2] += sc * v.z;
                    acc[i][3] += sc * v.w;
                }
            }
        }
    }

    float* Ob = O + (size_t)(b * Nn + mt * TM) * H;
#pragma unroll
    for (int i = 0; i < 8; i++)
        *(float4*)&Ob[(rg * 8 + i) * H + ct * 4] =
            make_float4(acc[i][0], acc[i][1], acc[i][2], acc[i][3]);
}

// ---------------------------------------------------------------------------
// Kernel 3: _fm epilogue.
// out[d,b,n,k] = num / (max(dx,eps)*max(dy,eps))
//   num = sum_l (x*y)[n,l] W2[k,l]; dx = sqrt(sum_l x^2 W2[k,l]); dy likewise
//   dir 0: x=h1, y=agg1; dir 1: x=h2, y=agg2. W2 = w_m*w_m.
// ---------------------------------------------------------------------------
__global__ void fm_kernel(const float* __restrict__ h1,
                          const float* __restrict__ h2,
                          const float* __restrict__ w_m,
                          float* __restrict__ out) {
    extern __shared__ float sm[];
    float* P  = sm;              // x*y   TM*LD
    float* XX = P + TM * LD;     // x*x
    float* YY = XX + TM * LD;    // y*y
    float* Ws = YY + TM * LD;    // W2 chunk (64 rows of k)

    const int tid = threadIdx.x;
    const int b = blockIdx.y, mt = blockIdx.x, dir = blockIdx.z;
    const float* X = (dir == 0 ? h1 : h2) + (size_t)(b * Nn + mt * TM) * H;
    const float* Y = (dir == 0 ? g_agg1 : g_agg2) + (size_t)(b * Nn + mt * TM) * H;
    float* Ob = out + (size_t)((dir * B + b) * Nn + mt * TM) * H;

    for (int i = tid; i < TM * (H / 4); i += 256) {
        int r = i >> 5, c4 = (i & 31) << 2;
        float4 xv = *(const float4*)&X[r * H + c4];
        float4 yv = *(const float4*)&Y[r * H + c4];
        *(float4*)&P[r * LD + c4]  = make_float4(xv.x * yv.x, xv.y * yv.y, xv.z * yv.z, xv.w * yv.w);
        *(float4*)&XX[r * LD + c4] = make_float4(xv.x * xv.x, xv.y * xv.y, xv.z * xv.z, xv.w * xv.w);
        *(float4*)&YY[r * LD + c4] = make_float4(yv.x * yv.x, yv.y * yv.y, yv.z * yv.z, yv.w * yv.w);
    }

    const int ty = tid >> 4, tx = tid & 15;
    const int r0 = ty * 4, c0 = tx * 4;

    for (int ch = 0; ch < 2; ++ch) {
        __syncthreads();  // products ready / previous Ws consumed
        for (int i = tid; i < TM * (H / 4); i += 256) {
            int r = i >> 5, c4 = (i & 31) << 2;
            float4 w = *(const float4*)&w_m[(size_t)(ch * TM + r) * H + c4];
            *(float4*)&Ws[r * LD + c4] =
                make_float4(w.x * w.x, w.y * w.y, w.z * w.z, w.w * w.w);
        }
        __syncthreads();

        float num[4][4], dxx[4][4], dyy[4][4];
#pragma unroll
        for (int i = 0; i < 4; i++)
#pragma unroll
            for (int j = 0; j < 4; j++) { num[i][j] = 0.f; dxx[i][j] = 0.f; dyy[i][j] = 0.f; }

#pragma unroll 2
        for (int l = 0; l < H; l += 4) {
            float4 p[4], xx[4], yy[4], w[4];
#pragma unroll
            for (int i = 0; i < 4; i++) {
                p[i]  = *(float4*)&P[(r0 + i) * LD + l];
                xx[i] = *(float4*)&XX[(r0 + i) * LD + l];
                yy[i] = *(float4*)&YY[(r0 + i) * LD + l];
            }
#pragma unroll
            for (int j = 0; j < 4; j++) w[j] = *(float4*)&Ws[(c0 + j) * LD + l];
#pragma unroll
            for (int i = 0; i < 4; i++)
#pragma unroll
                for (int j = 0; j < 4; j++) {
                    num[i][j] += p[i].x * w[j].x + p[i].y * w[j].y + p[i].z * w[j].z + p[i].w * w[j].w;
                    dxx[i][j] += xx[i].x * w[j].x + xx[i].y * w[j].y + xx[i].z * w[j].z + xx[i].w * w[j].w;
                    dyy[i][j] += yy[i].x * w[j].x + yy[i].y * w[j].y + yy[i].z * w[j].z + yy[i].w * w[j].w;
                }
        }

#pragma unroll
        for (int i = 0; i < 4; i++) {
            float4 o;
            float* op = &o.x;
#pragma unroll
            for (int j = 0; j < 4; j++) {
                float dx = fmaxf(sqrtf(dxx[i][j]), EPSF);
                float dy = fmaxf(sqrtf(dyy[i][j]), EPSF);
                op[j] = num[i][j] / (dx * dy);
            }
            *(float4*)&Ob[(r0 + i) * H + ch * TM + c0] = o;
        }
    }
}

// ---------------------------------------------------------------------------
extern "C" void kernel_launch(void* const* d_in, const int* in_sizes, int n_in,
                              void* d_out, int out_size) {
    const float* h1  = (const float*)d_in[0];
    const float* h2  = (const float*)d_in[1];
    const float* w_m = (const float*)d_in[2];
    float* out = (float*)d_out;

    constexpr int AGG_SMEM = (3 * TM * LD + TM * SLD) * (int)sizeof(float);  // ~119 KB
    constexpr int FM_SMEM  = (4 * TM * LD) * (int)sizeof(float);             // ~135 KB

    cudaFuncSetAttribute(agg_kernel, cudaFuncAttributeMaxDynamicSharedMemorySize, AGG_SMEM);
    cudaFuncSetAttribute(fm_kernel,  cudaFuncAttributeMaxDynamicSharedMemorySize, FM_SMEM);

    // 1) normalize rows of h1, h2
    normalize_kernel<<<(2 * B * Nn) / 8, 256>>>(h1, h2);

    // 2) fused bidirectional aggregation
    dim3 g(Nn / TM, B, 2);
    agg_kernel<<<g, 256, AGG_SMEM>>>(h1, h2);

    // 3) _fm epilogue -> out [2,B,N,H]
    fm_kernel<<<g, 256, FM_SMEM>>>(h1, h2, w_m, out);
}

// round 3
// speedup vs baseline: 8.0927x; 8.0927x over previous
#include <cuda_runtime.h>

#define EPSF 1e-8f
constexpr int B  = 8;
constexpr int Nn = 2048;
constexpr int H  = 128;
constexpr int TM = 64;          // fm tile rows
constexpr int LD = 132;         // padded leading dim (floats)
constexpr int SPL = 16;         // split-K factor for C = N^T H
constexpr int RC  = Nn / SPL;   // 128 rows per split

// Scratch (device globals: allocation-free rule)
__device__ float g_n1[B * Nn * H];
__device__ float g_n2[B * Nn * H];
__device__ float g_agg1[B * Nn * H];
__device__ float g_agg2[B * Nn * H];
__device__ float g_part[2 * B * SPL * H * H];   // split-K partials
__device__ float g_C[2 * B * H * H];            // w=0: C2=N2^T H2, w=1: C1=N1^T H1

// ---------------------------------------------------------------------------
// K1: row-normalize h1 -> g_n1, h2 -> g_n2. One warp per row (H=128).
// ---------------------------------------------------------------------------
__global__ void normalize_kernel(const float* __restrict__ h1,
                                 const float* __restrict__ h2) {
    int warp = (blockIdx.x * blockDim.x + threadIdx.x) >> 5;
    int lane = threadIdx.x & 31;
    const float* src;
    float* dst;
    int row;
    if (warp < B * Nn) { src = h1; dst = g_n1; row = warp; }
    else               { src = h2; dst = g_n2; row = warp - B * Nn; }

    float4 v = ((const float4*)(src + (size_t)row * H))[lane];
    float ss = v.x * v.x + v.y * v.y + v.z * v.z + v.w * v.w;
#pragma unroll
    for (int o = 16; o; o >>= 1) ss += __shfl_xor_sync(0xffffffffu, ss, o);
    float inv = 1.0f / fmaxf(sqrtf(ss), EPSF);
    ((float4*)(dst + (size_t)row * H))[lane] =
        make_float4(v.x * inv, v.y * inv, v.z * inv, v.w * inv);
}

// ---------------------------------------------------------------------------
// K2a: split-K partials of C = N^T H  [128x128] per (b, which, split).
//   which=0: N=g_n2, Hmat=h2  (-> C2, used by dir 0)
//   which=1: N=g_n1, Hmat=h1  (-> C1, used by dir 1)
// Block 256 threads = 16x16, each owns an 8x8 output micro-tile.
// ---------------------------------------------------------------------------
__global__ void cmat_partial_kernel(const float* __restrict__ h1,
                                    const float* __restrict__ h2) {
    extern __shared__ float sm[];
    float* Ns = sm;              // RC x LD
    float* Hs = sm + RC * LD;    // RC x LD

    const int s = blockIdx.x, b = blockIdx.y, w = blockIdx.z;
    const int tid = threadIdx.x;
    const float* Nsrc = (w == 0 ? g_n2 : g_n1) + (size_t)(b * Nn + s * RC) * H;
    const float* Hsrc = (w == 0 ? h2   : h1  ) + (size_t)(b * Nn + s * RC) * H;

    for (int i = tid; i < RC * (H / 4); i += 256) {
        int r = i >> 5, c4 = (i & 31) << 2;
        *(float4*)&Ns[r * LD + c4] = *(const float4*)&Nsrc[r * H + c4];
        *(float4*)&Hs[r * LD + c4] = *(const float4*)&Hsrc[r * H + c4];
    }
    __syncthreads();

    const int ty = tid >> 4, tx = tid & 15;
    const int k0 = ty * 8, h0 = tx * 8;

    float acc[8][8];
#pragma unroll
    for (int i = 0; i < 8; i++)
#pragma unroll
        for (int j = 0; j < 8; j++) acc[i][j] = 0.0f;

#pragma unroll 4
    for (int r = 0; r < RC; ++r) {
        float a[8], bb[8];
        *(float4*)&a[0]  = *(float4*)&Ns[r * LD + k0];
        *(float4*)&a[4]  = *(float4*)&Ns[r * LD + k0 + 4];
        *(float4*)&bb[0] = *(float4*)&Hs[r * LD + h0];
        *(float4*)&bb[4] = *(float4*)&Hs[r * LD + h0 + 4];
#pragma unroll
        for (int i = 0; i < 8; i++)
#pragma unroll
            for (int j = 0; j < 8; j++) acc[i][j] += a[i] * bb[j];
    }

    float* P = g_part + ((size_t)(w * B + b) * SPL + s) * (H * H);
#pragma unroll
    for (int i = 0; i < 8; i++) {
        *(float4*)&P[(k0 + i) * H + h0]     = make_float4(acc[i][0], acc[i][1], acc[i][2], acc[i][3]);
        *(float4*)&P[(k0 + i) * H + h0 + 4] = make_float4(acc[i][4], acc[i][5], acc[i][6], acc[i][7]);
    }
}

// ---------------------------------------------------------------------------
// K2b: reduce SPL partials -> g_C
// ---------------------------------------------------------------------------
__global__ void cmat_reduce_kernel() {
    const int b = blockIdx.y, w = blockIdx.z;
    const int e = blockIdx.x * 256 + threadIdx.x;     // 0 .. H*H-1
    const float* P = g_part + (size_t)(w * B + b) * SPL * (H * H);
    float sum = 0.0f;
#pragma unroll
    for (int s = 0; s < SPL; s++) sum += P[(size_t)s * (H * H) + e];
    g_C[(size_t)(w * B + b) * (H * H) + e] = sum;
}

// ---------------------------------------------------------------------------
// K3: apply — agg = N · C  [2048x128]·[128x128] per (b,dir).
//   dir 0: agg1 = n1 · C2;  dir 1: agg2 = n2 · C1.
// Tile 128 rows per block; 16x16 threads x 8x8 micro.
// ---------------------------------------------------------------------------
__global__ void apply_kernel() {
    extern __shared__ float sm[];
    float* Nt = sm;               // 128 x LD
    float* Cs = sm + 128 * LD;    // 128 x LD

    const int mt = blockIdx.x, b = blockIdx.y, dir = blockIdx.z;
    const int tid = threadIdx.x;
    const float* Nsrc = (dir == 0 ? g_n1 : g_n2) + (size_t)(b * Nn + mt * 128) * H;
    const float* Csrc = g_C + (size_t)(dir * B + b) * (H * H);
    float* O = (dir == 0 ? g_agg1 : g_agg2) + (size_t)(b * Nn + mt * 128) * H;

    for (int i = tid; i < 128 * (H / 4); i += 256) {
        int r = i >> 5, c4 = (i & 31) << 2;
        *(float4*)&Nt[r * LD + c4] = *(const float4*)&Nsrc[r * H + c4];
        *(float4*)&Cs[r * LD + c4] = *(const float4*)&Csrc[r * H + c4];
    }
    __syncthreads();

    const int ty = tid >> 4, tx = tid & 15;
    const int r0 = ty * 8, h0 = tx * 8;

    float acc[8][8];
#pragma unroll
    for (int i = 0; i < 8; i++)
#pragma unroll
        for (int j = 0; j < 8; j++) acc[i][j] = 0.0f;

#pragma unroll 2
    for (int k4 = 0; k4 < H; k4 += 4) {
        float4 a4[8];
#pragma unroll
        for (int i = 0; i < 8; i++) a4[i] = *(float4*)&Nt[(r0 + i) * LD + k4];
#pragma unroll
        for (int kk = 0; kk < 4; kk++) {
            float bb[8];
            *(float4*)&bb[0] = *(float4*)&Cs[(k4 + kk) * LD + h0];
            *(float4*)&bb[4] = *(float4*)&Cs[(k4 + kk) * LD + h0 + 4];
#pragma unroll
            for (int i = 0; i < 8; i++) {
                float av = (&a4[i].x)[kk];
#pragma unroll
                for (int j = 0; j < 8; j++) acc[i][j] += av * bb[j];
            }
        }
    }

#pragma unroll
    for (int i = 0; i < 8; i++) {
        *(float4*)&O[(r0 + i) * H + h0]     = make_float4(acc[i][0], acc[i][1], acc[i][2], acc[i][3]);
        *(float4*)&O[(r0 + i) * H + h0 + 4] = make_float4(acc[i][4], acc[i][5], acc[i][6], acc[i][7]);
    }
}

// ---------------------------------------------------------------------------
// K4: _fm epilogue.
// out[d,b,n,k] = num / (max(dx,eps)*max(dy,eps))
//   num = sum_l (x*y)[n,l] W2[k,l]; dx = sqrt(sum_l x^2 W2[k,l]); dy likewise
// ---------------------------------------------------------------------------
__global__ void fm_kernel(const float* __restrict__ h1,
                          const float* __restrict__ h2,
                          const float* __restrict__ w_m,
                          float* __restrict__ out) {
    extern __shared__ float sm[];
    float* P  = sm;              // x*y   TM*LD
    float* XX = P + TM * LD;     // x*x
    float* YY = XX + TM * LD;    // y*y
    float* Ws = YY + TM * LD;    // W2 chunk (64 rows of k)

    const int tid = threadIdx.x;
    const int b = blockIdx.y, mt = blockIdx.x, dir = blockIdx.z;
    const float* X = (dir == 0 ? h1 : h2) + (size_t)(b * Nn + mt * TM) * H;
    const float* Y = (dir == 0 ? g_agg1 : g_agg2) + (size_t)(b * Nn + mt * TM) * H;
    float* Ob = out + (size_t)((dir * B + b) * Nn + mt * TM) * H;

    for (int i = tid; i < TM * (H / 4); i += 256) {
        int r = i >> 5, c4 = (i & 31) << 2;
        float4 xv = *(const float4*)&X[r * H + c4];
        float4 yv = *(const float4*)&Y[r * H + c4];
        *(float4*)&P[r * LD + c4]  = make_float4(xv.x * yv.x, xv.y * yv.y, xv.z * yv.z, xv.w * yv.w);
        *(float4*)&XX[r * LD + c4] = make_float4(xv.x * xv.x, xv.y * xv.y, xv.z * xv.z, xv.w * xv.w);
        *(float4*)&YY[r * LD + c4] = make_float4(yv.x * yv.x, yv.y * yv.y, yv.z * yv.z, yv.w * yv.w);
    }

    const int ty = tid >> 4, tx = tid & 15;
    const int r0 = ty * 4, c0 = tx * 4;

    for (int ch = 0; ch < 2; ++ch) {
        __syncthreads();
        for (int i = tid; i < TM * (H / 4); i += 256) {
            int r = i >> 5, c4 = (i & 31) << 2;
            float4 w = *(const float4*)&w_m[(size_t)(ch * TM + r) * H + c4];
            *(float4*)&Ws[r * LD + c4] =
                make_float4(w.x * w.x, w.y * w.y, w.z * w.z, w.w * w.w);
        }
        __syncthreads();

        float num[4][4], dxx[4][4], dyy[4][4];
#pragma unroll
        for (int i = 0; i < 4; i++)
#pragma unroll
            for (int j = 0; j < 4; j++) { num[i][j] = 0.f; dxx[i][j] = 0.f; dyy[i][j] = 0.f; }

#pragma unroll 2
        for (int l = 0; l < H; l += 4) {
            float4 p[4], xx[4], yy[4], w[4];
#pragma unroll
            for (int i = 0; i < 4; i++) {
                p[i]  = *(float4*)&P[(r0 + i) * LD + l];
                xx[i] = *(float4*)&XX[(r0 + i) * LD + l];
                yy[i] = *(float4*)&YY[(r0 + i) * LD + l];
            }
#pragma unroll
            for (int j = 0; j < 4; j++) w[j] = *(float4*)&Ws[(c0 + j) * LD + l];
#pragma unroll
            for (int i = 0; i < 4; i++)
#pragma unroll
                for (int j = 0; j < 4; j++) {
                    num[i][j] += p[i].x * w[j].x + p[i].y * w[j].y + p[i].z * w[j].z + p[i].w * w[j].w;
                    dxx[i][j] += xx[i].x * w[j].x + xx[i].y * w[j].y + xx[i].z * w[j].z + xx[i].w * w[j].w;
                    dyy[i][j] += yy[i].x * w[j].x + yy[i].y * w[j].y + yy[i].z * w[j].z + yy[i].w * w[j].w;
                }
        }

#pragma unroll
        for (int i = 0; i < 4; i++) {
            float4 o;
            float* op = &o.x;
#pragma unroll
            for (int j = 0; j < 4; j++) {
                float dx = fmaxf(sqrtf(dxx[i][j]), EPSF);
                float dy = fmaxf(sqrtf(dyy[i][j]), EPSF);
                op[j] = num[i][j] / (dx * dy);
            }
            *(float4*)&Ob[(r0 + i) * H + ch * TM + c0] = o;
        }
    }
}

// ---------------------------------------------------------------------------
extern "C" void kernel_launch(void* const* d_in, const int* in_sizes, int n_in,
                              void* d_out, int out_size) {
    const float* h1  = (const float*)d_in[0];
    const float* h2  = (const float*)d_in[1];
    const float* w_m = (const float*)d_in[2];
    float* out = (float*)d_out;

    constexpr int SM2     = 2 * RC * LD * (int)sizeof(float);   // ~135 KB
    constexpr int FM_SMEM = 4 * TM * LD * (int)sizeof(float);   // ~135 KB

    cudaFuncSetAttribute(cmat_partial_kernel, cudaFuncAttributeMaxDynamicSharedMemorySize, SM2);
    cudaFuncSetAttribute(apply_kernel,        cudaFuncAttributeMaxDynamicSharedMemorySize, SM2);
    cudaFuncSetAttribute(fm_kernel,           cudaFuncAttributeMaxDynamicSharedMemorySize, FM_SMEM);

    // 1) normalize rows of h1, h2
    normalize_kernel<<<(2 * B * Nn) / 8, 256>>>(h1, h2);

    // 2) C = N^T H, split-K partials then reduce
    cmat_partial_kernel<<<dim3(SPL, B, 2), 256, SM2>>>(h1, h2);
    cmat_reduce_kernel<<<dim3(H * H / 256, B, 2), 256>>>();

    // 3) agg = N · C
    apply_kernel<<<dim3(Nn / 128, B, 2), 256, SM2>>>();

    // 4) _fm epilogue -> out [2,B,N,H]
    fm_kernel<<<dim3(Nn / TM, B, 2), 256, FM_SMEM>>>(h1, h2, w_m, out);
}